// round 1
// baseline (speedup 1.0000x reference)
#include <cuda_runtime.h>
#include <cuda_bf16.h>
#include <math.h>

// Problem constants
#define BATCH 2
#define SEQ   2048
#define EMB   2048
#define NHEAD 16
#define HDIM  128
#define F3E   6144          // 3*EMB

// Scratch (device globals; allocation-free)
__device__ float g_qkv[(size_t)BATCH * SEQ * F3E];   // [B,S,3E]  (q|k|v per head)
__device__ float g_ctx[(size_t)BATCH * SEQ * EMB];   // [B,S,E]

// ---------------------------------------------------------------------------
// SGEMM (NT): C[m,n] = sum_k A[m,k]*B[n,k] + bias[n]
// A: [M,K] row-major, B: [N,K] row-major. M%128==0, N%128==0, K%32==0.
// Block tile 128x128x32, 256 threads, 8x8 per thread.
// ---------------------------------------------------------------------------
__global__ void __launch_bounds__(256) sgemm_nt_bias(
    const float* __restrict__ A, const float* __restrict__ B,
    const float* __restrict__ bias, float* __restrict__ C,
    int M, int N, int K)
{
    __shared__ float As[128 * 33];   // As[row][k], stride 33
    __shared__ float Bs[32 * 133];   // Bs[k][col], stride 133

    const int tid = threadIdx.x;
    const int tx = tid & 15;         // 0..15
    const int ty = tid >> 4;         // 0..15
    const int m0 = blockIdx.y * 128;
    const int n0 = blockIdx.x * 128;

    const float* Ab = A + (size_t)m0 * K;
    const float* Bb = B + (size_t)n0 * K;

    float acc[8][8];
#pragma unroll
    for (int i = 0; i < 8; i++)
#pragma unroll
        for (int j = 0; j < 8; j++) acc[i][j] = 0.f;

    for (int k0 = 0; k0 < K; k0 += 32) {
        // Load A tile: 128 rows x 32 k
#pragma unroll
        for (int p = 0; p < 4; p++) {
            int id  = tid + p * 256;      // 0..1023 float4 ids
            int row = id >> 3;            // /8
            int c4  = id & 7;
            float4 v = *(const float4*)(Ab + (size_t)row * K + k0 + c4 * 4);
            float* dst = &As[row * 33 + c4 * 4];
            dst[0] = v.x; dst[1] = v.y; dst[2] = v.z; dst[3] = v.w;
        }
        // Load B tile: 128 cols x 32 k, store transposed Bs[k][col]
#pragma unroll
        for (int p = 0; p < 4; p++) {
            int id  = tid + p * 256;
            int col = id >> 3;
            int c4  = id & 7;
            float4 v = *(const float4*)(Bb + (size_t)col * K + k0 + c4 * 4);
            Bs[(c4 * 4 + 0) * 133 + col] = v.x;
            Bs[(c4 * 4 + 1) * 133 + col] = v.y;
            Bs[(c4 * 4 + 2) * 133 + col] = v.z;
            Bs[(c4 * 4 + 3) * 133 + col] = v.w;
        }
        __syncthreads();

#pragma unroll
        for (int kk = 0; kk < 32; kk++) {
            float a[8], b[8];
#pragma unroll
            for (int i = 0; i < 8; i++) a[i] = As[(ty + 16 * i) * 33 + kk];
#pragma unroll
            for (int j = 0; j < 8; j++) b[j] = Bs[kk * 133 + tx * 8 + j];
#pragma unroll
            for (int i = 0; i < 8; i++)
#pragma unroll
                for (int j = 0; j < 8; j++) acc[i][j] += a[i] * b[j];
        }
        __syncthreads();
    }

    // Epilogue: add bias, coalesced float4 stores
#pragma unroll
    for (int i = 0; i < 8; i++) {
        int row = m0 + ty + 16 * i;
        float* cp = C + (size_t)row * N + n0 + tx * 8;
        const float* bp = bias + n0 + tx * 8;
        float4 o0, o1;
        o0.x = acc[i][0] + bp[0]; o0.y = acc[i][1] + bp[1];
        o0.z = acc[i][2] + bp[2]; o0.w = acc[i][3] + bp[3];
        o1.x = acc[i][4] + bp[4]; o1.y = acc[i][5] + bp[5];
        o1.z = acc[i][6] + bp[6]; o1.w = acc[i][7] + bp[7];
        *(float4*)(cp)     = o0;
        *(float4*)(cp + 4) = o1;
    }
}

// ---------------------------------------------------------------------------
// RoPE: applied in-place to q and k inside g_qkv.
// qkv layout per (b,s): [q(16x128) | k(16x128) | v(16x128)]
// ---------------------------------------------------------------------------
__global__ void rope_kernel(float* __restrict__ qkv)
{
    int idx = blockIdx.x * blockDim.x + threadIdx.x;   // B*S*H*64 = 4194304
    if (idx >= BATCH * SEQ * NHEAD * 64) return;
    int i = idx & 63;
    int h = (idx >> 6) & 15;
    int s = (idx >> 10) & 2047;
    int b = idx >> 21;

    // inv_freq[i] = 10000^(-(2i)/128), computed in double for accuracy
    double ex   = (double)(2 * i) / 128.0;
    float invf  = (float)exp(-ex * 9.210340371976184);   // ln(10000)
    float ang   = (float)s * invf;
    float sn, cs;
    sincosf(ang, &sn, &cs);

    size_t base = ((size_t)(b * SEQ + s)) * F3E + (size_t)h * HDIM;
    float* q = qkv + base;
    float* k = qkv + base + EMB;

    float q1 = q[i], q2 = q[i + 64];
    q[i]      = q1 * cs - q2 * sn;
    q[i + 64] = q1 * sn + q2 * cs;
    float k1 = k[i], k2 = k[i + 64];
    k[i]      = k1 * cs - k2 * sn;
    k[i + 64] = k1 * sn + k2 * cs;
}

// ---------------------------------------------------------------------------
// Flash attention (fp32, causal, online softmax).
// Grid: (S/64, H, B). Block: 256 threads. Br=Bc=64, D=128.
// Smem: Qs/Ks/Vs 64x132 each + Ps 64x68 = 118784 bytes (dynamic).
// ---------------------------------------------------------------------------
#define QSTR 132
#define PSTR 68
#define FLASH_SMEM ((3 * 64 * QSTR + 64 * PSTR) * 4)

__global__ void __launch_bounds__(256) flash_kernel(
    const float* __restrict__ qkv, float* __restrict__ ctx)
{
    extern __shared__ float sm[];
    float* Qs = sm;
    float* Ks = sm + 64 * QSTR;
    float* Vs = sm + 2 * 64 * QSTR;
    float* Ps = sm + 3 * 64 * QSTR;

    const int tid = threadIdx.x;
    const int tx = tid & 15;     // 0..15
    const int ty = tid >> 4;     // 0..15
    const int rb = blockIdx.x;
    const int h  = blockIdx.y;
    const int b  = blockIdx.z;
    const int r0 = rb * 64;

    const float* qb = qkv + (size_t)b * SEQ * F3E + (size_t)h * HDIM;
    const float* kb = qb + EMB;
    const float* vb = qb + 2 * EMB;

    // Load Q tile (rows r0..r0+63, 128 floats each)
#pragma unroll
    for (int p = 0; p < 8; p++) {
        int id  = tid + p * 256;     // 0..2047 float4 ids
        int row = id >> 5;
        int c4  = id & 31;
        *(float4*)&Qs[row * QSTR + c4 * 4] =
            *(const float4*)(qb + (size_t)(r0 + row) * F3E + c4 * 4);
    }

    float m_i[4], l_i[4], acc[4][8];
#pragma unroll
    for (int i = 0; i < 4; i++) {
        m_i[i] = -1e30f; l_i[i] = 0.f;
#pragma unroll
        for (int c = 0; c < 8; c++) acc[i][c] = 0.f;
    }
    const float scale = 0.08838834764831845f;   // 1/sqrt(128)

    for (int kblk = 0; kblk <= rb; kblk++) {
        __syncthreads();   // prior iteration done with Ks/Vs/Ps
        const int c0 = kblk * 64;
        // Load K and V tiles
#pragma unroll
        for (int p = 0; p < 8; p++) {
            int id  = tid + p * 256;
            int row = id >> 5;
            int c4  = id & 31;
            *(float4*)&Ks[row * QSTR + c4 * 4] =
                *(const float4*)(kb + (size_t)(c0 + row) * F3E + c4 * 4);
            *(float4*)&Vs[row * QSTR + c4 * 4] =
                *(const float4*)(vb + (size_t)(c0 + row) * F3E + c4 * 4);
        }
        __syncthreads();

        // S = Q K^T : thread covers rows ty+16i, cols tx+16j
        float sc[4][4];
#pragma unroll
        for (int i = 0; i < 4; i++)
#pragma unroll
            for (int j = 0; j < 4; j++) sc[i][j] = 0.f;

#pragma unroll 4
        for (int k = 0; k < 128; k += 4) {
            float4 aq[4], bk4[4];
#pragma unroll
            for (int i = 0; i < 4; i++)
                aq[i] = *(const float4*)&Qs[(ty + 16 * i) * QSTR + k];
#pragma unroll
            for (int j = 0; j < 4; j++)
                bk4[j] = *(const float4*)&Ks[(tx + 16 * j) * QSTR + k];
#pragma unroll
            for (int i = 0; i < 4; i++)
#pragma unroll
                for (int j = 0; j < 4; j++) {
                    sc[i][j] += aq[i].x * bk4[j].x;
                    sc[i][j] += aq[i].y * bk4[j].y;
                    sc[i][j] += aq[i].z * bk4[j].z;
                    sc[i][j] += aq[i].w * bk4[j].w;
                }
        }

        const bool diag = (kblk == rb);
#pragma unroll
        for (int i = 0; i < 4; i++) {
            int grow = r0 + ty + 16 * i;
#pragma unroll
            for (int j = 0; j < 4; j++) {
                sc[i][j] *= scale;
                if (diag && (c0 + tx + 16 * j > grow)) sc[i][j] = -1e30f;
            }
        }

        // Online softmax per row (16 tx threads share a row; shfl within half-warp)
#pragma unroll
        for (int i = 0; i < 4; i++) {
            float mx = fmaxf(fmaxf(sc[i][0], sc[i][1]), fmaxf(sc[i][2], sc[i][3]));
#pragma unroll
            for (int o = 8; o >= 1; o >>= 1)
                mx = fmaxf(mx, __shfl_xor_sync(0xffffffffu, mx, o));
            float mnew = fmaxf(m_i[i], mx);
            float sum = 0.f;
#pragma unroll
            for (int j = 0; j < 4; j++) {
                sc[i][j] = __expf(sc[i][j] - mnew);
                sum += sc[i][j];
            }
#pragma unroll
            for (int o = 8; o >= 1; o >>= 1)
                sum += __shfl_xor_sync(0xffffffffu, sum, o);
            float alpha = __expf(m_i[i] - mnew);
            l_i[i] = l_i[i] * alpha + sum;
            m_i[i] = mnew;
#pragma unroll
            for (int c = 0; c < 8; c++) acc[i][c] *= alpha;
        }

        // Stage P to smem
#pragma unroll
        for (int i = 0; i < 4; i++)
#pragma unroll
            for (int j = 0; j < 4; j++)
                Ps[(ty + 16 * i) * PSTR + tx + 16 * j] = sc[i][j];
        __syncthreads();

        // O += P V : thread accumulates rows ty+16i, cols tx*8..tx*8+7
#pragma unroll 4
        for (int j = 0; j < 64; j++) {
            float4 v0 = *(const float4*)&Vs[j * QSTR + tx * 8];
            float4 v1 = *(const float4*)&Vs[j * QSTR + tx * 8 + 4];
#pragma unroll
            for (int i = 0; i < 4; i++) {
                float p = Ps[(ty + 16 * i) * PSTR + j];
                acc[i][0] += p * v0.x; acc[i][1] += p * v0.y;
                acc[i][2] += p * v0.z; acc[i][3] += p * v0.w;
                acc[i][4] += p * v1.x; acc[i][5] += p * v1.y;
                acc[i][6] += p * v1.z; acc[i][7] += p * v1.w;
            }
        }
    }

    // Epilogue: normalize and write ctx[b, row, h*128 + tx*8 + c]
#pragma unroll
    for (int i = 0; i < 4; i++) {
        float inv = 1.f / l_i[i];
        int row = r0 + ty + 16 * i;
        float* op = ctx + ((size_t)b * SEQ + row) * EMB + (size_t)h * HDIM + tx * 8;
        float4 o0, o1;
        o0.x = acc[i][0] * inv; o0.y = acc[i][1] * inv;
        o0.z = acc[i][2] * inv; o0.w = acc[i][3] * inv;
        o1.x = acc[i][4] * inv; o1.y = acc[i][5] * inv;
        o1.z = acc[i][6] * inv; o1.w = acc[i][7] * inv;
        *(float4*)(op)     = o0;
        *(float4*)(op + 4) = o1;
    }
}

// ---------------------------------------------------------------------------
// Launch
// ---------------------------------------------------------------------------
extern "C" void kernel_launch(void* const* d_in, const int* in_sizes, int n_in,
                              void* d_out, int out_size)
{
    const float* x      = (const float*)d_in[0];
    const float* wqkv_w = (const float*)d_in[1];
    const float* wqkv_b = (const float*)d_in[2];
    const float* out_w  = (const float*)d_in[3];
    const float* out_b  = (const float*)d_in[4];
    float* out = (float*)d_out;

    float* qkv = nullptr;
    float* ctx = nullptr;
    cudaGetSymbolAddress((void**)&qkv, g_qkv);
    cudaGetSymbolAddress((void**)&ctx, g_ctx);

    cudaFuncSetAttribute(flash_kernel,
                         cudaFuncAttributeMaxDynamicSharedMemorySize, FLASH_SMEM);

    // 1) QKV projection: [4096,2048] x [6144,2048]^T -> [4096,6144]
    sgemm_nt_bias<<<dim3(F3E / 128, (BATCH * SEQ) / 128), 256>>>(
        x, wqkv_w, wqkv_b, qkv, BATCH * SEQ, F3E, EMB);

    // 2) RoPE on q and k
    rope_kernel<<<(BATCH * SEQ * NHEAD * 64) / 256, 256>>>(qkv);

    // 3) Causal flash attention -> ctx [B,S,E]
    flash_kernel<<<dim3(SEQ / 64, NHEAD, BATCH), 256, FLASH_SMEM>>>(qkv, ctx);

    // 4) Output projection: [4096,2048] x [2048,2048]^T -> [4096,2048]
    sgemm_nt_bias<<<dim3(EMB / 128, (BATCH * SEQ) / 128), 256>>>(
        ctx, out_w, out_b, out, BATCH * SEQ, EMB, EMB);
}

// round 3
// speedup vs baseline: 1.8756x; 1.8756x over previous
#include <cuda_runtime.h>
#include <cuda_bf16.h>
#include <math.h>
#include <stdint.h>

// Problem constants
#define BATCH 2
#define SEQ   2048
#define EMB   2048
#define NHEAD 16
#define HDIM  128
#define F3E   6144          // 3*EMB
#define MTOT  (BATCH*SEQ)   // 4096

// ---------------------------------------------------------------------------
// Scratch (device globals; allocation-free)
// ---------------------------------------------------------------------------
__device__ float g_qkv[(size_t)BATCH * SEQ * F3E];   // [B,S,3E]
__device__ float g_ctx[(size_t)BATCH * SEQ * EMB];   // [B,S,E]

// bf16 hi/lo splits
__device__ __nv_bfloat16 g_xh[(size_t)MTOT * EMB];
__device__ __nv_bfloat16 g_xl[(size_t)MTOT * EMB];
__device__ __nv_bfloat16 g_wqh[(size_t)F3E * EMB];
__device__ __nv_bfloat16 g_wql[(size_t)F3E * EMB];
__device__ __nv_bfloat16 g_owh[(size_t)EMB * EMB];
__device__ __nv_bfloat16 g_owl[(size_t)EMB * EMB];
__device__ __nv_bfloat16 g_ch[(size_t)MTOT * EMB];
__device__ __nv_bfloat16 g_cl[(size_t)MTOT * EMB];

// ---------------------------------------------------------------------------
// fp32 -> bf16 hi/lo split (vectorized x4)
// ---------------------------------------------------------------------------
__global__ void split_kernel(const float* __restrict__ in,
                             __nv_bfloat16* __restrict__ hi,
                             __nv_bfloat16* __restrict__ lo, int n4)
{
    int i = blockIdx.x * blockDim.x + threadIdx.x;
    if (i >= n4) return;
    float4 v = ((const float4*)in)[i];

    __nv_bfloat16 hx = __float2bfloat16(v.x);
    __nv_bfloat16 hy = __float2bfloat16(v.y);
    __nv_bfloat16 hz = __float2bfloat16(v.z);
    __nv_bfloat16 hw = __float2bfloat16(v.w);
    __nv_bfloat16 lx = __float2bfloat16(v.x - __bfloat162float(hx));
    __nv_bfloat16 ly = __float2bfloat16(v.y - __bfloat162float(hy));
    __nv_bfloat16 lz = __float2bfloat16(v.z - __bfloat162float(hz));
    __nv_bfloat16 lw = __float2bfloat16(v.w - __bfloat162float(hw));

    __nv_bfloat162* hp = (__nv_bfloat162*)(hi + 4 * (size_t)i);
    __nv_bfloat162* lp = (__nv_bfloat162*)(lo + 4 * (size_t)i);
    hp[0] = __halves2bfloat162(hx, hy);
    hp[1] = __halves2bfloat162(hz, hw);
    lp[0] = __halves2bfloat162(lx, ly);
    lp[1] = __halves2bfloat162(lz, lw);
}

// ---------------------------------------------------------------------------
// bf16x3 GEMM via mma.sync (NT): C[m,n] = sum_k A[m,k]*B[n,k] + bias[n]
// Tile 128x128, K-chunks of 32, 2-stage cp.async pipeline.
// 8 warps; warp tile 32(M) x 64(N); atom m16n8k16.
// ---------------------------------------------------------------------------
#define KC      32                    // K per chunk
#define TSTR    40                    // smem row stride (bf16 elems), 80B
#define TILE_B  (128 * TSTR * 2)      // 10240 B per tile
#define STAGE_B (4 * TILE_B)          // Ah, Al, Bh, Bl
#define GEMM_SMEM (2 * STAGE_B)       // 81920 B

#define MMA_BF16(d, a, b) \
    asm volatile( \
        "mma.sync.aligned.m16n8k16.row.col.f32.bf16.bf16.f32 " \
        "{%0,%1,%2,%3}, {%4,%5,%6,%7}, {%8,%9}, {%0,%1,%2,%3};" \
        : "+f"((d)[0]), "+f"((d)[1]), "+f"((d)[2]), "+f"((d)[3]) \
        : "r"((a)[0]), "r"((a)[1]), "r"((a)[2]), "r"((a)[3]), \
          "r"((b)[0]), "r"((b)[1]))

__device__ __forceinline__ void cp_async16(void* smem_ptr, const void* gptr) {
    uint32_t saddr;
    asm("{ .reg .u64 t; cvta.to.shared.u64 t, %1; cvt.u32.u64 %0, t; }"
        : "=r"(saddr) : "l"(smem_ptr));
    asm volatile("cp.async.cg.shared.global [%0], [%1], 16;"
                 :: "r"(saddr), "l"(gptr));
}

__global__ void __launch_bounds__(256) gemm_mma_bf16x3(
    const __nv_bfloat16* __restrict__ Ah, const __nv_bfloat16* __restrict__ Al,
    const __nv_bfloat16* __restrict__ Bh, const __nv_bfloat16* __restrict__ Bl,
    const float* __restrict__ bias, float* __restrict__ C,
    int M, int N, int K)
{
    extern __shared__ char dsm[];

    const int tid = threadIdx.x;
    const int wid = tid >> 5;
    const int lane = tid & 31;
    const int gid = lane >> 2;        // group id 0..7
    const int tig = lane & 3;         // thread in group 0..3
    const int wm = wid & 3;           // warp m 0..3 (32 rows each)
    const int wn = wid >> 2;          // warp n 0..1 (64 cols each)
    const int m0 = blockIdx.y * 128;
    const int n0 = blockIdx.x * 128;

    float acc[2][8][4];
#pragma unroll
    for (int i = 0; i < 2; i++)
#pragma unroll
        for (int j = 0; j < 8; j++)
#pragma unroll
            for (int c = 0; c < 4; c++) acc[i][j][c] = 0.f;

    const int nch = K / KC;

    // Issue async loads for chunk `c` into stage buffer
    auto issue = [&](int c, int stage) {
        char* st = dsm + stage * STAGE_B;
        __nv_bfloat16* sAh = (__nv_bfloat16*)(st);
        __nv_bfloat16* sAl = (__nv_bfloat16*)(st + TILE_B);
        __nv_bfloat16* sBh = (__nv_bfloat16*)(st + 2 * TILE_B);
        __nv_bfloat16* sBl = (__nv_bfloat16*)(st + 3 * TILE_B);
        const int k0 = c * KC;
#pragma unroll
        for (int p = 0; p < 2; p++) {
            int id  = tid + p * 256;          // 0..511
            int row = id >> 2;                // 0..127
            int q   = id & 3;                 // 0..3 (8-elem groups)
            size_t ga = (size_t)(m0 + row) * K + k0 + q * 8;
            size_t gb = (size_t)(n0 + row) * K + k0 + q * 8;
            int so = row * TSTR + q * 8;
            cp_async16(sAh + so, Ah + ga);
            cp_async16(sAl + so, Al + ga);
            cp_async16(sBh + so, Bh + gb);
            cp_async16(sBl + so, Bl + gb);
        }
        asm volatile("cp.async.commit_group;" ::: "memory");
    };

    issue(0, 0);

    for (int c = 0; c < nch; c++) {
        if (c + 1 < nch) {
            issue(c + 1, (c + 1) & 1);
            asm volatile("cp.async.wait_group 1;" ::: "memory");
        } else {
            asm volatile("cp.async.wait_group 0;" ::: "memory");
        }
        __syncthreads();

        char* st = dsm + (c & 1) * STAGE_B;
        const __nv_bfloat16* sAh = (const __nv_bfloat16*)(st);
        const __nv_bfloat16* sAl = (const __nv_bfloat16*)(st + TILE_B);
        const __nv_bfloat16* sBh = (const __nv_bfloat16*)(st + 2 * TILE_B);
        const __nv_bfloat16* sBl = (const __nv_bfloat16*)(st + 3 * TILE_B);

#pragma unroll
        for (int kk = 0; kk < KC; kk += 16) {
            // A fragments (hi & lo) for 2 m-atoms
            uint32_t ah[2][4], al[2][4];
#pragma unroll
            for (int mi = 0; mi < 2; mi++) {
                int rbase = wm * 32 + mi * 16 + gid;
                int kbase = kk + tig * 2;
                ah[mi][0] = *(const uint32_t*)(sAh + rbase * TSTR + kbase);
                ah[mi][1] = *(const uint32_t*)(sAh + (rbase + 8) * TSTR + kbase);
                ah[mi][2] = *(const uint32_t*)(sAh + rbase * TSTR + kbase + 8);
                ah[mi][3] = *(const uint32_t*)(sAh + (rbase + 8) * TSTR + kbase + 8);
                al[mi][0] = *(const uint32_t*)(sAl + rbase * TSTR + kbase);
                al[mi][1] = *(const uint32_t*)(sAl + (rbase + 8) * TSTR + kbase);
                al[mi][2] = *(const uint32_t*)(sAl + rbase * TSTR + kbase + 8);
                al[mi][3] = *(const uint32_t*)(sAl + (rbase + 8) * TSTR + kbase + 8);
            }
#pragma unroll
            for (int nj = 0; nj < 8; nj++) {
                int col = wn * 64 + nj * 8 + gid;
                int kbase = kk + tig * 2;
                uint32_t bh[2], bl[2];
                bh[0] = *(const uint32_t*)(sBh + col * TSTR + kbase);
                bh[1] = *(const uint32_t*)(sBh + col * TSTR + kbase + 8);
                bl[0] = *(const uint32_t*)(sBl + col * TSTR + kbase);
                bl[1] = *(const uint32_t*)(sBl + col * TSTR + kbase + 8);
#pragma unroll
                for (int mi = 0; mi < 2; mi++) {
                    MMA_BF16(acc[mi][nj], ah[mi], bh);
                    MMA_BF16(acc[mi][nj], ah[mi], bl);
                    MMA_BF16(acc[mi][nj], al[mi], bh);
                }
            }
        }
        __syncthreads();
    }

    // Epilogue: add bias, store fp32
#pragma unroll
    for (int mi = 0; mi < 2; mi++) {
        int row = m0 + wm * 32 + mi * 16 + gid;
#pragma unroll
        for (int nj = 0; nj < 8; nj++) {
            int col = n0 + wn * 64 + nj * 8 + tig * 2;
            float2 bv = *(const float2*)(bias + col);
            float2 o0, o1;
            o0.x = acc[mi][nj][0] + bv.x;
            o0.y = acc[mi][nj][1] + bv.y;
            o1.x = acc[mi][nj][2] + bv.x;
            o1.y = acc[mi][nj][3] + bv.y;
            *(float2*)(C + (size_t)row * N + col)       = o0;
            *(float2*)(C + (size_t)(row + 8) * N + col) = o1;
        }
    }
}

// ---------------------------------------------------------------------------
// RoPE: applied in-place to q and k inside g_qkv.
// ---------------------------------------------------------------------------
__global__ void rope_kernel(float* __restrict__ qkv)
{
    int idx = blockIdx.x * blockDim.x + threadIdx.x;
    if (idx >= BATCH * SEQ * NHEAD * 64) return;
    int i = idx & 63;
    int h = (idx >> 6) & 15;
    int s = (idx >> 10) & 2047;
    int b = idx >> 21;

    double ex  = (double)(2 * i) / 128.0;
    float invf = (float)exp(-ex * 9.210340371976184);
    float ang  = (float)s * invf;
    float sn, cs;
    sincosf(ang, &sn, &cs);

    size_t base = ((size_t)(b * SEQ + s)) * F3E + (size_t)h * HDIM;
    float* q = qkv + base;
    float* k = qkv + base + EMB;

    float q1 = q[i], q2 = q[i + 64];
    q[i]      = q1 * cs - q2 * sn;
    q[i + 64] = q1 * sn + q2 * cs;
    float k1 = k[i], k2 = k[i + 64];
    k[i]      = k1 * cs - k2 * sn;
    k[i + 64] = k1 * sn + k2 * cs;
}

// ---------------------------------------------------------------------------
// Flash attention (fp32, causal, online softmax).
// ---------------------------------------------------------------------------
#define QSTR 132
#define PSTR 68
#define FLASH_SMEM ((3 * 64 * QSTR + 64 * PSTR) * 4)

__global__ void __launch_bounds__(256) flash_kernel(
    const float* __restrict__ qkv, float* __restrict__ ctx)
{
    extern __shared__ float sm[];
    float* Qs = sm;
    float* Ks = sm + 64 * QSTR;
    float* Vs = sm + 2 * 64 * QSTR;
    float* Ps = sm + 3 * 64 * QSTR;

    const int tid = threadIdx.x;
    const int tx = tid & 15;
    const int ty = tid >> 4;
    const int rb = blockIdx.x;
    const int h  = blockIdx.y;
    const int b  = blockIdx.z;
    const int r0 = rb * 64;

    const float* qb = qkv + (size_t)b * SEQ * F3E + (size_t)h * HDIM;
    const float* kb = qb + EMB;
    const float* vb = qb + 2 * EMB;

#pragma unroll
    for (int p = 0; p < 8; p++) {
        int id  = tid + p * 256;
        int row = id >> 5;
        int c4  = id & 31;
        *(float4*)&Qs[row * QSTR + c4 * 4] =
            *(const float4*)(qb + (size_t)(r0 + row) * F3E + c4 * 4);
    }

    float m_i[4], l_i[4], acc[4][8];
#pragma unroll
    for (int i = 0; i < 4; i++) {
        m_i[i] = -1e30f; l_i[i] = 0.f;
#pragma unroll
        for (int c = 0; c < 8; c++) acc[i][c] = 0.f;
    }
    const float scale = 0.08838834764831845f;

    for (int kblk = 0; kblk <= rb; kblk++) {
        __syncthreads();
        const int c0 = kblk * 64;
#pragma unroll
        for (int p = 0; p < 8; p++) {
            int id  = tid + p * 256;
            int row = id >> 5;
            int c4  = id & 31;
            *(float4*)&Ks[row * QSTR + c4 * 4] =
                *(const float4*)(kb + (size_t)(c0 + row) * F3E + c4 * 4);
            *(float4*)&Vs[row * QSTR + c4 * 4] =
                *(const float4*)(vb + (size_t)(c0 + row) * F3E + c4 * 4);
        }
        __syncthreads();

        float sc[4][4];
#pragma unroll
        for (int i = 0; i < 4; i++)
#pragma unroll
            for (int j = 0; j < 4; j++) sc[i][j] = 0.f;

#pragma unroll 4
        for (int k = 0; k < 128; k += 4) {
            float4 aq[4], bk4[4];
#pragma unroll
            for (int i = 0; i < 4; i++)
                aq[i] = *(const float4*)&Qs[(ty + 16 * i) * QSTR + k];
#pragma unroll
            for (int j = 0; j < 4; j++)
                bk4[j] = *(const float4*)&Ks[(tx + 16 * j) * QSTR + k];
#pragma unroll
            for (int i = 0; i < 4; i++)
#pragma unroll
                for (int j = 0; j < 4; j++) {
                    sc[i][j] += aq[i].x * bk4[j].x;
                    sc[i][j] += aq[i].y * bk4[j].y;
                    sc[i][j] += aq[i].z * bk4[j].z;
                    sc[i][j] += aq[i].w * bk4[j].w;
                }
        }

        const bool diag = (kblk == rb);
#pragma unroll
        for (int i = 0; i < 4; i++) {
            int grow = r0 + ty + 16 * i;
#pragma unroll
            for (int j = 0; j < 4; j++) {
                sc[i][j] *= scale;
                if (diag && (c0 + tx + 16 * j > grow)) sc[i][j] = -1e30f;
            }
        }

#pragma unroll
        for (int i = 0; i < 4; i++) {
            float mx = fmaxf(fmaxf(sc[i][0], sc[i][1]), fmaxf(sc[i][2], sc[i][3]));
#pragma unroll
            for (int o = 8; o >= 1; o >>= 1)
                mx = fmaxf(mx, __shfl_xor_sync(0xffffffffu, mx, o));
            float mnew = fmaxf(m_i[i], mx);
            float sum = 0.f;
#pragma unroll
            for (int j = 0; j < 4; j++) {
                sc[i][j] = __expf(sc[i][j] - mnew);
                sum += sc[i][j];
            }
#pragma unroll
            for (int o = 8; o >= 1; o >>= 1)
                sum += __shfl_xor_sync(0xffffffffu, sum, o);
            float alpha = __expf(m_i[i] - mnew);
            l_i[i] = l_i[i] * alpha + sum;
            m_i[i] = mnew;
#pragma unroll
            for (int c = 0; c < 8; c++) acc[i][c] *= alpha;
        }

#pragma unroll
        for (int i = 0; i < 4; i++)
#pragma unroll
            for (int j = 0; j < 4; j++)
                Ps[(ty + 16 * i) * PSTR + tx + 16 * j] = sc[i][j];
        __syncthreads();

#pragma unroll 4
        for (int j = 0; j < 64; j++) {
            float4 v0 = *(const float4*)&Vs[j * QSTR + tx * 8];
            float4 v1 = *(const float4*)&Vs[j * QSTR + tx * 8 + 4];
#pragma unroll
            for (int i = 0; i < 4; i++) {
                float p = Ps[(ty + 16 * i) * PSTR + j];
                acc[i][0] += p * v0.x; acc[i][1] += p * v0.y;
                acc[i][2] += p * v0.z; acc[i][3] += p * v0.w;
                acc[i][4] += p * v1.x; acc[i][5] += p * v1.y;
                acc[i][6] += p * v1.z; acc[i][7] += p * v1.w;
            }
        }
    }

#pragma unroll
    for (int i = 0; i < 4; i++) {
        float inv = 1.f / l_i[i];
        int row = r0 + ty + 16 * i;
        float* op = ctx + ((size_t)b * SEQ + row) * EMB + (size_t)h * HDIM + tx * 8;
        float4 o0, o1;
        o0.x = acc[i][0] * inv; o0.y = acc[i][1] * inv;
        o0.z = acc[i][2] * inv; o0.w = acc[i][3] * inv;
        o1.x = acc[i][4] * inv; o1.y = acc[i][5] * inv;
        o1.z = acc[i][6] * inv; o1.w = acc[i][7] * inv;
        *(float4*)(op)     = o0;
        *(float4*)(op + 4) = o1;
    }
}

// ---------------------------------------------------------------------------
// Launch
// ---------------------------------------------------------------------------
extern "C" void kernel_launch(void* const* d_in, const int* in_sizes, int n_in,
                              void* d_out, int out_size)
{
    const float* x      = (const float*)d_in[0];
    const float* wqkv_w = (const float*)d_in[1];
    const float* wqkv_b = (const float*)d_in[2];
    const float* out_w  = (const float*)d_in[3];
    const float* out_b  = (const float*)d_in[4];
    float* out = (float*)d_out;

    float *qkv, *ctx;
    __nv_bfloat16 *xh, *xl, *wqh, *wql, *owh, *owl, *ch, *cl;
    cudaGetSymbolAddress((void**)&qkv, g_qkv);
    cudaGetSymbolAddress((void**)&ctx, g_ctx);
    cudaGetSymbolAddress((void**)&xh, g_xh);
    cudaGetSymbolAddress((void**)&xl, g_xl);
    cudaGetSymbolAddress((void**)&wqh, g_wqh);
    cudaGetSymbolAddress((void**)&wql, g_wql);
    cudaGetSymbolAddress((void**)&owh, g_owh);
    cudaGetSymbolAddress((void**)&owl, g_owl);
    cudaGetSymbolAddress((void**)&ch, g_ch);
    cudaGetSymbolAddress((void**)&cl, g_cl);

    cudaFuncSetAttribute(flash_kernel,
                         cudaFuncAttributeMaxDynamicSharedMemorySize, FLASH_SMEM);
    cudaFuncSetAttribute(gemm_mma_bf16x3,
                         cudaFuncAttributeMaxDynamicSharedMemorySize, GEMM_SMEM);

    // 0) Split inputs to bf16 hi/lo
    {
        int n4 = (MTOT * EMB) / 4;
        split_kernel<<<(n4 + 255) / 256, 256>>>(x, xh, xl, n4);
    }
    {
        int n4 = (F3E * EMB) / 4;
        split_kernel<<<(n4 + 255) / 256, 256>>>(wqkv_w, wqh, wql, n4);
    }
    {
        int n4 = (EMB * EMB) / 4;
        split_kernel<<<(n4 + 255) / 256, 256>>>(out_w, owh, owl, n4);
    }

    // 1) QKV projection: [4096,2048] x [6144,2048]^T
    gemm_mma_bf16x3<<<dim3(F3E / 128, MTOT / 128), 256, GEMM_SMEM>>>(
        xh, xl, wqh, wql, wqkv_b, qkv, MTOT, F3E, EMB);

    // 2) RoPE
    rope_kernel<<<(BATCH * SEQ * NHEAD * 64) / 256, 256>>>(qkv);

    // 3) Causal flash attention
    flash_kernel<<<dim3(SEQ / 64, NHEAD, BATCH), 256, FLASH_SMEM>>>(qkv, ctx);

    // 4) Split ctx, output projection
    {
        int n4 = (MTOT * EMB) / 4;
        split_kernel<<<(n4 + 255) / 256, 256>>>(ctx, ch, cl, n4);
    }
    gemm_mma_bf16x3<<<dim3(EMB / 128, MTOT / 128), 256, GEMM_SMEM>>>(
        ch, cl, owh, owl, out_b, out, MTOT, EMB, EMB);
}

// round 4
// speedup vs baseline: 2.1051x; 1.1223x over previous
#include <cuda_runtime.h>
#include <cuda_bf16.h>
#include <math.h>
#include <stdint.h>

// Problem constants
#define BATCH 2
#define SEQ   2048
#define EMB   2048
#define NHEAD 16
#define HDIM  128
#define F3E   6144          // 3*EMB
#define MTOT  (BATCH*SEQ)   // 4096

// ---------------------------------------------------------------------------
// Scratch (device globals; allocation-free)
// ---------------------------------------------------------------------------
__device__ float g_qkv[(size_t)BATCH * SEQ * F3E];   // [B,S,3E]
__device__ float g_ctx[(size_t)BATCH * SEQ * EMB];   // [B,S,E]

// bf16 hi/lo splits
__device__ __nv_bfloat16 g_xh[(size_t)MTOT * EMB];
__device__ __nv_bfloat16 g_xl[(size_t)MTOT * EMB];
__device__ __nv_bfloat16 g_wqh[(size_t)F3E * EMB];
__device__ __nv_bfloat16 g_wql[(size_t)F3E * EMB];
__device__ __nv_bfloat16 g_owh[(size_t)EMB * EMB];
__device__ __nv_bfloat16 g_owl[(size_t)EMB * EMB];
__device__ __nv_bfloat16 g_ch[(size_t)MTOT * EMB];
__device__ __nv_bfloat16 g_cl[(size_t)MTOT * EMB];

// ---------------------------------------------------------------------------
// fp32 -> bf16 hi/lo split (vectorized x4)
// ---------------------------------------------------------------------------
__global__ void split_kernel(const float* __restrict__ in,
                             __nv_bfloat16* __restrict__ hi,
                             __nv_bfloat16* __restrict__ lo, int n4)
{
    int i = blockIdx.x * blockDim.x + threadIdx.x;
    if (i >= n4) return;
    float4 v = ((const float4*)in)[i];

    __nv_bfloat16 hx = __float2bfloat16(v.x);
    __nv_bfloat16 hy = __float2bfloat16(v.y);
    __nv_bfloat16 hz = __float2bfloat16(v.z);
    __nv_bfloat16 hw = __float2bfloat16(v.w);
    __nv_bfloat16 lx = __float2bfloat16(v.x - __bfloat162float(hx));
    __nv_bfloat16 ly = __float2bfloat16(v.y - __bfloat162float(hy));
    __nv_bfloat16 lz = __float2bfloat16(v.z - __bfloat162float(hz));
    __nv_bfloat16 lw = __float2bfloat16(v.w - __bfloat162float(hw));

    __nv_bfloat162* hp = (__nv_bfloat162*)(hi + 4 * (size_t)i);
    __nv_bfloat162* lp = (__nv_bfloat162*)(lo + 4 * (size_t)i);
    hp[0] = __halves2bfloat162(hx, hy);
    hp[1] = __halves2bfloat162(hz, hw);
    lp[0] = __halves2bfloat162(lx, ly);
    lp[1] = __halves2bfloat162(lz, lw);
}

// ---------------------------------------------------------------------------
// mma.sync helpers
// ---------------------------------------------------------------------------
#define MMA_BF16(d, a, b) \
    asm volatile( \
        "mma.sync.aligned.m16n8k16.row.col.f32.bf16.bf16.f32 " \
        "{%0,%1,%2,%3}, {%4,%5,%6,%7}, {%8,%9}, {%0,%1,%2,%3};" \
        : "+f"((d)[0]), "+f"((d)[1]), "+f"((d)[2]), "+f"((d)[3]) \
        : "r"((a)[0]), "r"((a)[1]), "r"((a)[2]), "r"((a)[3]), \
          "r"((b)[0]), "r"((b)[1]))

__device__ __forceinline__ void cp_async16(void* smem_ptr, const void* gptr) {
    uint32_t saddr;
    asm("{ .reg .u64 t; cvta.to.shared.u64 t, %1; cvt.u32.u64 %0, t; }"
        : "=r"(saddr) : "l"(smem_ptr));
    asm volatile("cp.async.cg.shared.global [%0], [%1], 16;"
                 :: "r"(saddr), "l"(gptr));
}

__device__ __forceinline__ uint32_t pack_bf16(float a, float b) {
    __nv_bfloat162 t = __float22bfloat162_rn(make_float2(a, b));
    return *(uint32_t*)&t;
}

// ---------------------------------------------------------------------------
// bf16x3 GEMM via mma.sync (NT): C[m,n] = sum_k A[m,k]*B[n,k] + bias[n]
// Tile 128x128, K-chunks of 32, 2-stage cp.async pipeline. (unchanged R3)
// ---------------------------------------------------------------------------
#define KC      32
#define TSTR    40
#define TILE_B  (128 * TSTR * 2)
#define STAGE_B (4 * TILE_B)
#define GEMM_SMEM (2 * STAGE_B)

__global__ void __launch_bounds__(256) gemm_mma_bf16x3(
    const __nv_bfloat16* __restrict__ Ah, const __nv_bfloat16* __restrict__ Al,
    const __nv_bfloat16* __restrict__ Bh, const __nv_bfloat16* __restrict__ Bl,
    const float* __restrict__ bias, float* __restrict__ C,
    int M, int N, int K)
{
    extern __shared__ char dsm[];

    const int tid = threadIdx.x;
    const int wid = tid >> 5;
    const int lane = tid & 31;
    const int gid = lane >> 2;
    const int tig = lane & 3;
    const int wm = wid & 3;
    const int wn = wid >> 2;
    const int m0 = blockIdx.y * 128;
    const int n0 = blockIdx.x * 128;

    float acc[2][8][4];
#pragma unroll
    for (int i = 0; i < 2; i++)
#pragma unroll
        for (int j = 0; j < 8; j++)
#pragma unroll
            for (int c = 0; c < 4; c++) acc[i][j][c] = 0.f;

    const int nch = K / KC;

    auto issue = [&](int c, int stage) {
        char* st = dsm + stage * STAGE_B;
        __nv_bfloat16* sAh = (__nv_bfloat16*)(st);
        __nv_bfloat16* sAl = (__nv_bfloat16*)(st + TILE_B);
        __nv_bfloat16* sBh = (__nv_bfloat16*)(st + 2 * TILE_B);
        __nv_bfloat16* sBl = (__nv_bfloat16*)(st + 3 * TILE_B);
        const int k0 = c * KC;
#pragma unroll
        for (int p = 0; p < 2; p++) {
            int id  = tid + p * 256;
            int row = id >> 2;
            int q   = id & 3;
            size_t ga = (size_t)(m0 + row) * K + k0 + q * 8;
            size_t gb = (size_t)(n0 + row) * K + k0 + q * 8;
            int so = row * TSTR + q * 8;
            cp_async16(sAh + so, Ah + ga);
            cp_async16(sAl + so, Al + ga);
            cp_async16(sBh + so, Bh + gb);
            cp_async16(sBl + so, Bl + gb);
        }
        asm volatile("cp.async.commit_group;" ::: "memory");
    };

    issue(0, 0);

    for (int c = 0; c < nch; c++) {
        if (c + 1 < nch) {
            issue(c + 1, (c + 1) & 1);
            asm volatile("cp.async.wait_group 1;" ::: "memory");
        } else {
            asm volatile("cp.async.wait_group 0;" ::: "memory");
        }
        __syncthreads();

        char* st = dsm + (c & 1) * STAGE_B;
        const __nv_bfloat16* sAh = (const __nv_bfloat16*)(st);
        const __nv_bfloat16* sAl = (const __nv_bfloat16*)(st + TILE_B);
        const __nv_bfloat16* sBh = (const __nv_bfloat16*)(st + 2 * TILE_B);
        const __nv_bfloat16* sBl = (const __nv_bfloat16*)(st + 3 * TILE_B);

#pragma unroll
        for (int kk = 0; kk < KC; kk += 16) {
            uint32_t ah[2][4], al[2][4];
#pragma unroll
            for (int mi = 0; mi < 2; mi++) {
                int rbase = wm * 32 + mi * 16 + gid;
                int kbase = kk + tig * 2;
                ah[mi][0] = *(const uint32_t*)(sAh + rbase * TSTR + kbase);
                ah[mi][1] = *(const uint32_t*)(sAh + (rbase + 8) * TSTR + kbase);
                ah[mi][2] = *(const uint32_t*)(sAh + rbase * TSTR + kbase + 8);
                ah[mi][3] = *(const uint32_t*)(sAh + (rbase + 8) * TSTR + kbase + 8);
                al[mi][0] = *(const uint32_t*)(sAl + rbase * TSTR + kbase);
                al[mi][1] = *(const uint32_t*)(sAl + (rbase + 8) * TSTR + kbase);
                al[mi][2] = *(const uint32_t*)(sAl + rbase * TSTR + kbase + 8);
                al[mi][3] = *(const uint32_t*)(sAl + (rbase + 8) * TSTR + kbase + 8);
            }
#pragma unroll
            for (int nj = 0; nj < 8; nj++) {
                int col = wn * 64 + nj * 8 + gid;
                int kbase = kk + tig * 2;
                uint32_t bh[2], bl[2];
                bh[0] = *(const uint32_t*)(sBh + col * TSTR + kbase);
                bh[1] = *(const uint32_t*)(sBh + col * TSTR + kbase + 8);
                bl[0] = *(const uint32_t*)(sBl + col * TSTR + kbase);
                bl[1] = *(const uint32_t*)(sBl + col * TSTR + kbase + 8);
#pragma unroll
                for (int mi = 0; mi < 2; mi++) {
                    MMA_BF16(acc[mi][nj], ah[mi], bh);
                    MMA_BF16(acc[mi][nj], ah[mi], bl);
                    MMA_BF16(acc[mi][nj], al[mi], bh);
                }
            }
        }
        __syncthreads();
    }

#pragma unroll
    for (int mi = 0; mi < 2; mi++) {
        int row = m0 + wm * 32 + mi * 16 + gid;
#pragma unroll
        for (int nj = 0; nj < 8; nj++) {
            int col = n0 + wn * 64 + nj * 8 + tig * 2;
            float2 bv = *(const float2*)(bias + col);
            float2 o0, o1;
            o0.x = acc[mi][nj][0] + bv.x;
            o0.y = acc[mi][nj][1] + bv.y;
            o1.x = acc[mi][nj][2] + bv.x;
            o1.y = acc[mi][nj][3] + bv.y;
            *(float2*)(C + (size_t)row * N + col)       = o0;
            *(float2*)(C + (size_t)(row + 8) * N + col) = o1;
        }
    }
}

// ---------------------------------------------------------------------------
// RoPE: applied in-place to q and k inside g_qkv.
// ---------------------------------------------------------------------------
__global__ void rope_kernel(float* __restrict__ qkv)
{
    int idx = blockIdx.x * blockDim.x + threadIdx.x;
    if (idx >= BATCH * SEQ * NHEAD * 64) return;
    int i = idx & 63;
    int h = (idx >> 6) & 15;
    int s = (idx >> 10) & 2047;
    int b = idx >> 21;

    double ex  = (double)(2 * i) / 128.0;
    float invf = (float)exp(-ex * 9.210340371976184);
    float ang  = (float)s * invf;
    float sn, cs;
    sincosf(ang, &sn, &cs);

    size_t base = ((size_t)(b * SEQ + s)) * F3E + (size_t)h * HDIM;
    float* q = qkv + base;
    float* k = qkv + base + EMB;

    float q1 = q[i], q2 = q[i + 64];
    q[i]      = q1 * cs - q2 * sn;
    q[i + 64] = q1 * sn + q2 * cs;
    float k1 = k[i], k2 = k[i + 64];
    k[i]      = k1 * cs - k2 * sn;
    k[i + 64] = k1 * sn + k2 * cs;
}

// ---------------------------------------------------------------------------
// Flash attention via mma.sync bf16x3 (causal, online softmax, fp32 state).
// Br=64 (4 warps x 16 rows), Bc=64, D=128. 128 threads.
// smem: Qh/Ql/Kh/Kl [64][136] bf16; Vth/Vtl [128][72] bf16 (V transposed).
// ---------------------------------------------------------------------------
#define QKS 136
#define VTS 72
#define OFF_QH 0
#define OFF_QL (64 * QKS)
#define OFF_KH (2 * 64 * QKS)
#define OFF_KL (3 * 64 * QKS)
#define OFF_VH (4 * 64 * QKS)
#define OFF_VL (4 * 64 * QKS + 128 * VTS)
#define FLASH_SMEM ((4 * 64 * QKS + 2 * 128 * VTS) * 2)

__global__ void __launch_bounds__(128) flash_mma_kernel(
    const float* __restrict__ qkv, float* __restrict__ ctx)
{
    extern __shared__ __nv_bfloat16 fsm[];
    __nv_bfloat16* Qh  = fsm + OFF_QH;
    __nv_bfloat16* Ql  = fsm + OFF_QL;
    __nv_bfloat16* Kh  = fsm + OFF_KH;
    __nv_bfloat16* Kl  = fsm + OFF_KL;
    __nv_bfloat16* Vth = fsm + OFF_VH;
    __nv_bfloat16* Vtl = fsm + OFF_VL;

    const int tid  = threadIdx.x;
    const int wid  = tid >> 5;
    const int lane = tid & 31;
    const int gid  = lane >> 2;
    const int tig  = lane & 3;
    const int rb = gridDim.x - 1 - blockIdx.x;   // heavy blocks first
    const int h  = blockIdx.y;
    const int b  = blockIdx.z;
    const int r0 = rb * 64;

    const float* qb = qkv + (size_t)b * SEQ * F3E + (size_t)h * HDIM;
    const float* kb = qb + EMB;
    const float* vb = qb + 2 * EMB;

    const float scale = 0.08838834764831845f;   // 1/sqrt(128)

    // Load + split Q tile (64 rows x 128)
#pragma unroll
    for (int p = 0; p < 16; p++) {
        int id  = tid + p * 128;       // 0..2047 float4 ids
        int row = id >> 5;
        int c4  = (id & 31) * 4;
        float4 v = *(const float4*)(qb + (size_t)(r0 + row) * F3E + c4);
        __nv_bfloat16 h0 = __float2bfloat16(v.x), h1 = __float2bfloat16(v.y);
        __nv_bfloat16 h2 = __float2bfloat16(v.z), h3 = __float2bfloat16(v.w);
        __nv_bfloat162* hp = (__nv_bfloat162*)&Qh[row * QKS + c4];
        hp[0] = __halves2bfloat162(h0, h1);
        hp[1] = __halves2bfloat162(h2, h3);
        __nv_bfloat162* lp = (__nv_bfloat162*)&Ql[row * QKS + c4];
        lp[0] = __halves2bfloat162(__float2bfloat16(v.x - __bfloat162float(h0)),
                                   __float2bfloat16(v.y - __bfloat162float(h1)));
        lp[1] = __halves2bfloat162(__float2bfloat16(v.z - __bfloat162float(h2)),
                                   __float2bfloat16(v.w - __bfloat162float(h3)));
    }

    float m0r = -1e30f, m1r = -1e30f, l0r = 0.f, l1r = 0.f;
    float o[16][4];
#pragma unroll
    for (int na = 0; na < 16; na++)
#pragma unroll
        for (int c = 0; c < 4; c++) o[na][c] = 0.f;

    for (int kblk = 0; kblk <= rb; kblk++) {
        const int c0 = kblk * 64;
        __syncthreads();   // previous iteration done reading K/V

        // Load + split K; load + split + transpose V
#pragma unroll
        for (int p = 0; p < 16; p++) {
            int id  = tid + p * 128;
            int row = id >> 5;
            int c4  = (id & 31) * 4;
            float4 v = *(const float4*)(kb + (size_t)(c0 + row) * F3E + c4);
            __nv_bfloat16 h0 = __float2bfloat16(v.x), h1 = __float2bfloat16(v.y);
            __nv_bfloat16 h2 = __float2bfloat16(v.z), h3 = __float2bfloat16(v.w);
            __nv_bfloat162* hp = (__nv_bfloat162*)&Kh[row * QKS + c4];
            hp[0] = __halves2bfloat162(h0, h1);
            hp[1] = __halves2bfloat162(h2, h3);
            __nv_bfloat162* lp = (__nv_bfloat162*)&Kl[row * QKS + c4];
            lp[0] = __halves2bfloat162(__float2bfloat16(v.x - __bfloat162float(h0)),
                                       __float2bfloat16(v.y - __bfloat162float(h1)));
            lp[1] = __halves2bfloat162(__float2bfloat16(v.z - __bfloat162float(h2)),
                                       __float2bfloat16(v.w - __bfloat162float(h3)));

            float4 w = *(const float4*)(vb + (size_t)(c0 + row) * F3E + c4);
            __nv_bfloat16 g0 = __float2bfloat16(w.x), g1 = __float2bfloat16(w.y);
            __nv_bfloat16 g2 = __float2bfloat16(w.z), g3 = __float2bfloat16(w.w);
            Vth[(c4 + 0) * VTS + row] = g0;
            Vth[(c4 + 1) * VTS + row] = g1;
            Vth[(c4 + 2) * VTS + row] = g2;
            Vth[(c4 + 3) * VTS + row] = g3;
            Vtl[(c4 + 0) * VTS + row] = __float2bfloat16(w.x - __bfloat162float(g0));
            Vtl[(c4 + 1) * VTS + row] = __float2bfloat16(w.y - __bfloat162float(g1));
            Vtl[(c4 + 2) * VTS + row] = __float2bfloat16(w.z - __bfloat162float(g2));
            Vtl[(c4 + 3) * VTS + row] = __float2bfloat16(w.w - __bfloat162float(g3));
        }
        __syncthreads();

        // ---- S = Q K^T (3-term) ----
        float sc[8][4];
#pragma unroll
        for (int nj = 0; nj < 8; nj++)
#pragma unroll
            for (int c = 0; c < 4; c++) sc[nj][c] = 0.f;

#pragma unroll
        for (int ka = 0; ka < 8; ka++) {
            const int arow = wid * 16 + gid;
            const int kcol = ka * 16 + 2 * tig;
            uint32_t ah[4], al[4];
            ah[0] = *(const uint32_t*)&Qh[arow * QKS + kcol];
            ah[1] = *(const uint32_t*)&Qh[(arow + 8) * QKS + kcol];
            ah[2] = *(const uint32_t*)&Qh[arow * QKS + kcol + 8];
            ah[3] = *(const uint32_t*)&Qh[(arow + 8) * QKS + kcol + 8];
            al[0] = *(const uint32_t*)&Ql[arow * QKS + kcol];
            al[1] = *(const uint32_t*)&Ql[(arow + 8) * QKS + kcol];
            al[2] = *(const uint32_t*)&Ql[arow * QKS + kcol + 8];
            al[3] = *(const uint32_t*)&Ql[(arow + 8) * QKS + kcol + 8];
#pragma unroll
            for (int nj = 0; nj < 8; nj++) {
                const int brow = nj * 8 + gid;
                uint32_t bh[2], bl[2];
                bh[0] = *(const uint32_t*)&Kh[brow * QKS + kcol];
                bh[1] = *(const uint32_t*)&Kh[brow * QKS + kcol + 8];
                bl[0] = *(const uint32_t*)&Kl[brow * QKS + kcol];
                bl[1] = *(const uint32_t*)&Kl[brow * QKS + kcol + 8];
                MMA_BF16(sc[nj], ah, bh);
                MMA_BF16(sc[nj], ah, bl);
                MMA_BF16(sc[nj], al, bh);
            }
        }

        // ---- scale + causal mask ----
        const bool diag = (kblk == rb);
        const int grow0 = r0 + wid * 16 + gid;
#pragma unroll
        for (int nj = 0; nj < 8; nj++) {
            int col = c0 + nj * 8 + 2 * tig;
            sc[nj][0] *= scale; sc[nj][1] *= scale;
            sc[nj][2] *= scale; sc[nj][3] *= scale;
            if (diag) {
                if (col     > grow0)     sc[nj][0] = -1e30f;
                if (col + 1 > grow0)     sc[nj][1] = -1e30f;
                if (col     > grow0 + 8) sc[nj][2] = -1e30f;
                if (col + 1 > grow0 + 8) sc[nj][3] = -1e30f;
            }
        }

        // ---- online softmax (rows gid, gid+8; quad reduction) ----
        float mx0 = -1e30f, mx1 = -1e30f;
#pragma unroll
        for (int nj = 0; nj < 8; nj++) {
            mx0 = fmaxf(mx0, fmaxf(sc[nj][0], sc[nj][1]));
            mx1 = fmaxf(mx1, fmaxf(sc[nj][2], sc[nj][3]));
        }
        mx0 = fmaxf(mx0, __shfl_xor_sync(0xffffffffu, mx0, 1));
        mx0 = fmaxf(mx0, __shfl_xor_sync(0xffffffffu, mx0, 2));
        mx1 = fmaxf(mx1, __shfl_xor_sync(0xffffffffu, mx1, 1));
        mx1 = fmaxf(mx1, __shfl_xor_sync(0xffffffffu, mx1, 2));

        float mn0 = fmaxf(m0r, mx0);
        float mn1 = fmaxf(m1r, mx1);
        float al0 = __expf(m0r - mn0);
        float al1 = __expf(m1r - mn1);

        float s0 = 0.f, s1 = 0.f;
#pragma unroll
        for (int nj = 0; nj < 8; nj++) {
            sc[nj][0] = __expf(sc[nj][0] - mn0);
            sc[nj][1] = __expf(sc[nj][1] - mn0);
            sc[nj][2] = __expf(sc[nj][2] - mn1);
            sc[nj][3] = __expf(sc[nj][3] - mn1);
            s0 += sc[nj][0] + sc[nj][1];
            s1 += sc[nj][2] + sc[nj][3];
        }
        s0 += __shfl_xor_sync(0xffffffffu, s0, 1);
        s0 += __shfl_xor_sync(0xffffffffu, s0, 2);
        s1 += __shfl_xor_sync(0xffffffffu, s1, 1);
        s1 += __shfl_xor_sync(0xffffffffu, s1, 2);

        l0r = l0r * al0 + s0;
        l1r = l1r * al1 + s1;
        m0r = mn0; m1r = mn1;

#pragma unroll
        for (int na = 0; na < 16; na++) {
            o[na][0] *= al0; o[na][1] *= al0;
            o[na][2] *= al1; o[na][3] *= al1;
        }

        // ---- O += P V (3-term; P fragments from score regs) ----
#pragma unroll
        for (int ka2 = 0; ka2 < 4; ka2++) {
            const int j0 = 2 * ka2, j1 = 2 * ka2 + 1;
            uint32_t aph[4], apl[4];
            {
                float p0 = sc[j0][0], p1 = sc[j0][1];
                float p2 = sc[j0][2], p3 = sc[j0][3];
                float q0 = sc[j1][0], q1 = sc[j1][1];
                float q2 = sc[j1][2], q3 = sc[j1][3];
                aph[0] = pack_bf16(p0, p1);
                aph[1] = pack_bf16(p2, p3);
                aph[2] = pack_bf16(q0, q1);
                aph[3] = pack_bf16(q2, q3);
                __nv_bfloat162 t0 = *(__nv_bfloat162*)&aph[0];
                __nv_bfloat162 t1 = *(__nv_bfloat162*)&aph[1];
                __nv_bfloat162 t2 = *(__nv_bfloat162*)&aph[2];
                __nv_bfloat162 t3 = *(__nv_bfloat162*)&aph[3];
                apl[0] = pack_bf16(p0 - __bfloat162float(t0.x), p1 - __bfloat162float(t0.y));
                apl[1] = pack_bf16(p2 - __bfloat162float(t1.x), p3 - __bfloat162float(t1.y));
                apl[2] = pack_bf16(q0 - __bfloat162float(t2.x), q1 - __bfloat162float(t2.y));
                apl[3] = pack_bf16(q2 - __bfloat162float(t3.x), q3 - __bfloat162float(t3.y));
            }
            const int vrow = ka2 * 16 + 2 * tig;
#pragma unroll
            for (int na = 0; na < 16; na++) {
                const int dcol = na * 8 + gid;
                uint32_t bh[2], bl[2];
                bh[0] = *(const uint32_t*)&Vth[dcol * VTS + vrow];
                bh[1] = *(const uint32_t*)&Vth[dcol * VTS + vrow + 8];
                bl[0] = *(const uint32_t*)&Vtl[dcol * VTS + vrow];
                bl[1] = *(const uint32_t*)&Vtl[dcol * VTS + vrow + 8];
                MMA_BF16(o[na], aph, bh);
                MMA_BF16(o[na], aph, bl);
                MMA_BF16(o[na], apl, bh);
            }
        }
    }

    // ---- epilogue: normalize, write ctx ----
    float inv0 = 1.f / l0r;
    float inv1 = 1.f / l1r;
    int row = r0 + wid * 16 + gid;
    float* op0 = ctx + ((size_t)b * SEQ + row) * EMB + (size_t)h * HDIM;
    float* op1 = ctx + ((size_t)b * SEQ + row + 8) * EMB + (size_t)h * HDIM;
#pragma unroll
    for (int na = 0; na < 16; na++) {
        int col = na * 8 + 2 * tig;
        *(float2*)(op0 + col) = make_float2(o[na][0] * inv0, o[na][1] * inv0);
        *(float2*)(op1 + col) = make_float2(o[na][2] * inv1, o[na][3] * inv1);
    }
}

// ---------------------------------------------------------------------------
// Launch
// ---------------------------------------------------------------------------
extern "C" void kernel_launch(void* const* d_in, const int* in_sizes, int n_in,
                              void* d_out, int out_size)
{
    const float* x      = (const float*)d_in[0];
    const float* wqkv_w = (const float*)d_in[1];
    const float* wqkv_b = (const float*)d_in[2];
    const float* out_w  = (const float*)d_in[3];
    const float* out_b  = (const float*)d_in[4];
    float* out = (float*)d_out;

    float *qkv, *ctx;
    __nv_bfloat16 *xh, *xl, *wqh, *wql, *owh, *owl, *ch, *cl;
    cudaGetSymbolAddress((void**)&qkv, g_qkv);
    cudaGetSymbolAddress((void**)&ctx, g_ctx);
    cudaGetSymbolAddress((void**)&xh, g_xh);
    cudaGetSymbolAddress((void**)&xl, g_xl);
    cudaGetSymbolAddress((void**)&wqh, g_wqh);
    cudaGetSymbolAddress((void**)&wql, g_wql);
    cudaGetSymbolAddress((void**)&owh, g_owh);
    cudaGetSymbolAddress((void**)&owl, g_owl);
    cudaGetSymbolAddress((void**)&ch, g_ch);
    cudaGetSymbolAddress((void**)&cl, g_cl);

    cudaFuncSetAttribute(gemm_mma_bf16x3,
                         cudaFuncAttributeMaxDynamicSharedMemorySize, GEMM_SMEM);
    cudaFuncSetAttribute(flash_mma_kernel,
                         cudaFuncAttributeMaxDynamicSharedMemorySize, FLASH_SMEM);

    // 0) Split inputs to bf16 hi/lo
    {
        int n4 = (MTOT * EMB) / 4;
        split_kernel<<<(n4 + 255) / 256, 256>>>(x, xh, xl, n4);
    }
    {
        int n4 = (F3E * EMB) / 4;
        split_kernel<<<(n4 + 255) / 256, 256>>>(wqkv_w, wqh, wql, n4);
    }
    {
        int n4 = (EMB * EMB) / 4;
        split_kernel<<<(n4 + 255) / 256, 256>>>(out_w, owh, owl, n4);
    }

    // 1) QKV projection: [4096,2048] x [6144,2048]^T
    gemm_mma_bf16x3<<<dim3(F3E / 128, MTOT / 128), 256, GEMM_SMEM>>>(
        xh, xl, wqh, wql, wqkv_b, qkv, MTOT, F3E, EMB);

    // 2) RoPE
    rope_kernel<<<(BATCH * SEQ * NHEAD * 64) / 256, 256>>>(qkv);

    // 3) Causal flash attention (mma.sync bf16x3)
    flash_mma_kernel<<<dim3(SEQ / 64, NHEAD, BATCH), 128, FLASH_SMEM>>>(qkv, ctx);

    // 4) Split ctx, output projection
    {
        int n4 = (MTOT * EMB) / 4;
        split_kernel<<<(n4 + 255) / 256, 256>>>(ctx, ch, cl, n4);
    }
    gemm_mma_bf16x3<<<dim3(EMB / 128, MTOT / 128), 256, GEMM_SMEM>>>(
        ch, cl, owh, owl, out_b, out, MTOT, EMB, EMB);
}

// round 5
// speedup vs baseline: 2.9970x; 1.4237x over previous
#include <cuda_runtime.h>
#include <cuda_bf16.h>
#include <math.h>
#include <stdint.h>

// Problem constants
#define BATCH 2
#define SEQ   2048
#define EMB   2048
#define NHEAD 16
#define HDIM  128
#define F3E   6144          // 3*EMB
#define MTOT  (BATCH*SEQ)   // 4096

// ---------------------------------------------------------------------------
// Scratch (device globals; allocation-free)
// ---------------------------------------------------------------------------
__device__ float g_qkv[(size_t)BATCH * SEQ * F3E];   // [B,S,3E]
__device__ float g_ctx[(size_t)BATCH * SEQ * EMB];   // [B,S,E]

// bf16 hi/lo splits
__device__ __nv_bfloat16 g_xh[(size_t)MTOT * EMB];
__device__ __nv_bfloat16 g_xl[(size_t)MTOT * EMB];
__device__ __nv_bfloat16 g_wqh[(size_t)F3E * EMB];
__device__ __nv_bfloat16 g_wql[(size_t)F3E * EMB];
__device__ __nv_bfloat16 g_owh[(size_t)EMB * EMB];
__device__ __nv_bfloat16 g_owl[(size_t)EMB * EMB];
__device__ __nv_bfloat16 g_ch[(size_t)MTOT * EMB];
__device__ __nv_bfloat16 g_cl[(size_t)MTOT * EMB];

// ---------------------------------------------------------------------------
// fp32 -> bf16 hi/lo split (vectorized x4)
// ---------------------------------------------------------------------------
__global__ void split_kernel(const float* __restrict__ in,
                             __nv_bfloat16* __restrict__ hi,
                             __nv_bfloat16* __restrict__ lo, int n4)
{
    int i = blockIdx.x * blockDim.x + threadIdx.x;
    if (i >= n4) return;
    float4 v = ((const float4*)in)[i];

    __nv_bfloat16 hx = __float2bfloat16(v.x);
    __nv_bfloat16 hy = __float2bfloat16(v.y);
    __nv_bfloat16 hz = __float2bfloat16(v.z);
    __nv_bfloat16 hw = __float2bfloat16(v.w);
    __nv_bfloat16 lx = __float2bfloat16(v.x - __bfloat162float(hx));
    __nv_bfloat16 ly = __float2bfloat16(v.y - __bfloat162float(hy));
    __nv_bfloat16 lz = __float2bfloat16(v.z - __bfloat162float(hz));
    __nv_bfloat16 lw = __float2bfloat16(v.w - __bfloat162float(hw));

    __nv_bfloat162* hp = (__nv_bfloat162*)(hi + 4 * (size_t)i);
    __nv_bfloat162* lp = (__nv_bfloat162*)(lo + 4 * (size_t)i);
    hp[0] = __halves2bfloat162(hx, hy);
    hp[1] = __halves2bfloat162(hz, hw);
    lp[0] = __halves2bfloat162(lx, ly);
    lp[1] = __halves2bfloat162(lz, lw);
}

// ---------------------------------------------------------------------------
// mma.sync / ldmatrix helpers
// ---------------------------------------------------------------------------
#define MMA_BF16(d, a, b) \
    asm volatile( \
        "mma.sync.aligned.m16n8k16.row.col.f32.bf16.bf16.f32 " \
        "{%0,%1,%2,%3}, {%4,%5,%6,%7}, {%8,%9}, {%0,%1,%2,%3};" \
        : "+f"((d)[0]), "+f"((d)[1]), "+f"((d)[2]), "+f"((d)[3]) \
        : "r"((a)[0]), "r"((a)[1]), "r"((a)[2]), "r"((a)[3]), \
          "r"((b)[0]), "r"((b)[1]))

#define LDSM4(r, addr) \
    asm volatile("ldmatrix.sync.aligned.m8n8.x4.shared.b16 {%0,%1,%2,%3}, [%4];" \
        : "=r"((r)[0]), "=r"((r)[1]), "=r"((r)[2]), "=r"((r)[3]) : "r"(addr))

#define LDSM4T(r, addr) \
    asm volatile("ldmatrix.sync.aligned.m8n8.x4.trans.shared.b16 {%0,%1,%2,%3}, [%4];" \
        : "=r"((r)[0]), "=r"((r)[1]), "=r"((r)[2]), "=r"((r)[3]) : "r"(addr))

__device__ __forceinline__ uint32_t smem_u32(const void* p) {
    uint32_t a;
    asm("{ .reg .u64 t; cvta.to.shared.u64 t, %1; cvt.u32.u64 %0, t; }"
        : "=r"(a) : "l"(p));
    return a;
}

__device__ __forceinline__ void cp_async16(void* smem_ptr, const void* gptr) {
    uint32_t saddr = smem_u32(smem_ptr);
    asm volatile("cp.async.cg.shared.global [%0], [%1], 16;"
                 :: "r"(saddr), "l"(gptr));
}

__device__ __forceinline__ uint32_t pack_bf16(float a, float b) {
    __nv_bfloat162 t = __float22bfloat162_rn(make_float2(a, b));
    return *(uint32_t*)&t;
}

// ---------------------------------------------------------------------------
// bf16x3 GEMM via mma.sync + ldmatrix (NT): C = A B^T + bias
// Tile 128x128, K-chunks of 32, 2-stage cp.async pipeline.
// ---------------------------------------------------------------------------
#define KC      32
#define TSTR    40
#define TILE_B  (128 * TSTR * 2)
#define STAGE_B (4 * TILE_B)
#define GEMM_SMEM (2 * STAGE_B)

__global__ void __launch_bounds__(256) gemm_mma_bf16x3(
    const __nv_bfloat16* __restrict__ Ah, const __nv_bfloat16* __restrict__ Al,
    const __nv_bfloat16* __restrict__ Bh, const __nv_bfloat16* __restrict__ Bl,
    const float* __restrict__ bias, float* __restrict__ C,
    int M, int N, int K)
{
    extern __shared__ char dsm[];

    const int tid = threadIdx.x;
    const int wid = tid >> 5;
    const int lane = tid & 31;
    const int gid = lane >> 2;
    const int tig = lane & 3;
    const int wm = wid & 3;
    const int wn = wid >> 2;
    const int m0 = blockIdx.y * 128;
    const int n0 = blockIdx.x * 128;

    // ldmatrix per-lane row/k selectors
    const int laneA_row  = wm * 32 + (lane & 15);
    const int laneA_ksel = (lane >> 4) * 8;
    const int laneB_row  = wn * 64 + (lane & 7) + ((lane & 16) ? 8 : 0);
    const int laneB_ksel = (lane & 8) ? 8 : 0;

    const uint32_t sb = smem_u32(dsm);

    float acc[2][8][4];
#pragma unroll
    for (int i = 0; i < 2; i++)
#pragma unroll
        for (int j = 0; j < 8; j++)
#pragma unroll
            for (int c = 0; c < 4; c++) acc[i][j][c] = 0.f;

    const int nch = K / KC;

    auto issue = [&](int c, int stage) {
        char* st = dsm + stage * STAGE_B;
        __nv_bfloat16* sAh = (__nv_bfloat16*)(st);
        __nv_bfloat16* sAl = (__nv_bfloat16*)(st + TILE_B);
        __nv_bfloat16* sBh = (__nv_bfloat16*)(st + 2 * TILE_B);
        __nv_bfloat16* sBl = (__nv_bfloat16*)(st + 3 * TILE_B);
        const int k0 = c * KC;
#pragma unroll
        for (int p = 0; p < 2; p++) {
            int id  = tid + p * 256;
            int row = id >> 2;
            int q   = id & 3;
            size_t ga = (size_t)(m0 + row) * K + k0 + q * 8;
            size_t gb = (size_t)(n0 + row) * K + k0 + q * 8;
            int so = row * TSTR + q * 8;
            cp_async16(sAh + so, Ah + ga);
            cp_async16(sAl + so, Al + ga);
            cp_async16(sBh + so, Bh + gb);
            cp_async16(sBl + so, Bl + gb);
        }
        asm volatile("cp.async.commit_group;" ::: "memory");
    };

    issue(0, 0);

    for (int c = 0; c < nch; c++) {
        if (c + 1 < nch) {
            issue(c + 1, (c + 1) & 1);
            asm volatile("cp.async.wait_group 1;" ::: "memory");
        } else {
            asm volatile("cp.async.wait_group 0;" ::: "memory");
        }
        __syncthreads();

        const uint32_t stb = sb + (c & 1) * STAGE_B;

#pragma unroll
        for (int kk = 0; kk < KC; kk += 16) {
            uint32_t ah[2][4], al[2][4];
            uint32_t aA = stb + (uint32_t)((laneA_row * TSTR + kk + laneA_ksel) * 2);
            LDSM4(ah[0], aA);
            LDSM4(ah[1], aA + 16 * TSTR * 2);
            LDSM4(al[0], aA + TILE_B);
            LDSM4(al[1], aA + TILE_B + 16 * TSTR * 2);

#pragma unroll
            for (int njp = 0; njp < 4; njp++) {
                uint32_t bA = stb + 2 * TILE_B +
                    (uint32_t)(((laneB_row + njp * 16) * TSTR + kk + laneB_ksel) * 2);
                uint32_t bh4[4], bl4[4];
                LDSM4(bh4, bA);
                LDSM4(bl4, bA + TILE_B);
#pragma unroll
                for (int mi = 0; mi < 2; mi++) {
                    MMA_BF16(acc[mi][2 * njp],     ah[mi], bh4);
                    MMA_BF16(acc[mi][2 * njp],     ah[mi], bl4);
                    MMA_BF16(acc[mi][2 * njp],     al[mi], bh4);
                    MMA_BF16(acc[mi][2 * njp + 1], ah[mi], bh4 + 2);
                    MMA_BF16(acc[mi][2 * njp + 1], ah[mi], bl4 + 2);
                    MMA_BF16(acc[mi][2 * njp + 1], al[mi], bh4 + 2);
                }
            }
        }
        __syncthreads();
    }

#pragma unroll
    for (int mi = 0; mi < 2; mi++) {
        int row = m0 + wm * 32 + mi * 16 + gid;
#pragma unroll
        for (int nj = 0; nj < 8; nj++) {
            int col = n0 + wn * 64 + nj * 8 + tig * 2;
            float2 bv = *(const float2*)(bias + col);
            float2 o0, o1;
            o0.x = acc[mi][nj][0] + bv.x;
            o0.y = acc[mi][nj][1] + bv.y;
            o1.x = acc[mi][nj][2] + bv.x;
            o1.y = acc[mi][nj][3] + bv.y;
            *(float2*)(C + (size_t)row * N + col)       = o0;
            *(float2*)(C + (size_t)(row + 8) * N + col) = o1;
        }
    }
}

// ---------------------------------------------------------------------------
// RoPE: applied in-place to q and k inside g_qkv.
// ---------------------------------------------------------------------------
__global__ void rope_kernel(float* __restrict__ qkv)
{
    int idx = blockIdx.x * blockDim.x + threadIdx.x;
    if (idx >= BATCH * SEQ * NHEAD * 64) return;
    int i = idx & 63;
    int h = (idx >> 6) & 15;
    int s = (idx >> 10) & 2047;
    int b = idx >> 21;

    double ex  = (double)(2 * i) / 128.0;
    float invf = (float)exp(-ex * 9.210340371976184);
    float ang  = (float)s * invf;
    float sn, cs;
    sincosf(ang, &sn, &cs);

    size_t base = ((size_t)(b * SEQ + s)) * F3E + (size_t)h * HDIM;
    float* q = qkv + base;
    float* k = qkv + base + EMB;

    float q1 = q[i], q2 = q[i + 64];
    q[i]      = q1 * cs - q2 * sn;
    q[i + 64] = q1 * sn + q2 * cs;
    float k1 = k[i], k2 = k[i + 64];
    k[i]      = k1 * cs - k2 * sn;
    k[i + 64] = k1 * sn + k2 * cs;
}

// ---------------------------------------------------------------------------
// Flash attention via mma.sync bf16x3 + ldmatrix (causal, online softmax).
// Br=64 (4 warps x 16 rows), Bc=64, D=128. 128 threads.
// smem: Qh/Ql/Kh/Kl/Vh/Vl all [64][136] bf16 (V row-major; PV uses ldmatrix.trans)
// ---------------------------------------------------------------------------
#define QKS 136
#define OFF_QH 0
#define OFF_QL (64 * QKS)
#define OFF_KH (2 * 64 * QKS)
#define OFF_KL (3 * 64 * QKS)
#define OFF_VH (4 * 64 * QKS)
#define OFF_VL (5 * 64 * QKS)
#define FLASH_SMEM (6 * 64 * QKS * 2)

__global__ void __launch_bounds__(128) flash_mma_kernel(
    const float* __restrict__ qkv, float* __restrict__ ctx)
{
    extern __shared__ __nv_bfloat16 fsm[];
    __nv_bfloat16* Qh = fsm + OFF_QH;
    __nv_bfloat16* Ql = fsm + OFF_QL;
    __nv_bfloat16* Kh = fsm + OFF_KH;
    __nv_bfloat16* Kl = fsm + OFF_KL;
    __nv_bfloat16* Vh = fsm + OFF_VH;
    __nv_bfloat16* Vl = fsm + OFF_VL;

    const int tid  = threadIdx.x;
    const int wid  = tid >> 5;
    const int lane = tid & 31;
    const int gid  = lane >> 2;
    const int tig  = lane & 3;
    const int rb = gridDim.x - 1 - blockIdx.x;   // heavy blocks first
    const int h  = blockIdx.y;
    const int b  = blockIdx.z;
    const int r0 = rb * 64;

    const float* qb = qkv + (size_t)b * SEQ * F3E + (size_t)h * HDIM;
    const float* kb = qb + EMB;
    const float* vb = qb + 2 * EMB;

    const float scale = 0.08838834764831845f;   // 1/sqrt(128)

    // ldmatrix lane selectors
    const int aRow  = wid * 16 + (lane & 15);        // Q A-frags
    const int aKsel = (lane >> 4) * 8;
    const int bRow  = (lane & 7) + ((lane & 16) ? 8 : 0);   // K B-frags
    const int bKsel = (lane & 8) ? 8 : 0;
    const int vTrow = (lane & 7) + ((lane & 8) ? 8 : 0);    // V trans B-frags
    const int vDsel = (lane & 16) ? 8 : 0;

    const uint32_t QhB = smem_u32(Qh);
    const uint32_t QlB = smem_u32(Ql);
    const uint32_t KhB = smem_u32(Kh);
    const uint32_t KlB = smem_u32(Kl);
    const uint32_t VhB = smem_u32(Vh);
    const uint32_t VlB = smem_u32(Vl);

    // Load + split Q tile (64 rows x 128)
#pragma unroll
    for (int p = 0; p < 16; p++) {
        int id  = tid + p * 128;
        int row = id >> 5;
        int c4  = (id & 31) * 4;
        float4 v = *(const float4*)(qb + (size_t)(r0 + row) * F3E + c4);
        __nv_bfloat16 h0 = __float2bfloat16(v.x), h1 = __float2bfloat16(v.y);
        __nv_bfloat16 h2 = __float2bfloat16(v.z), h3 = __float2bfloat16(v.w);
        __nv_bfloat162* hp = (__nv_bfloat162*)&Qh[row * QKS + c4];
        hp[0] = __halves2bfloat162(h0, h1);
        hp[1] = __halves2bfloat162(h2, h3);
        __nv_bfloat162* lp = (__nv_bfloat162*)&Ql[row * QKS + c4];
        lp[0] = __halves2bfloat162(__float2bfloat16(v.x - __bfloat162float(h0)),
                                   __float2bfloat16(v.y - __bfloat162float(h1)));
        lp[1] = __halves2bfloat162(__float2bfloat16(v.z - __bfloat162float(h2)),
                                   __float2bfloat16(v.w - __bfloat162float(h3)));
    }

    float m0r = -1e30f, m1r = -1e30f, l0r = 0.f, l1r = 0.f;
    float o[16][4];
#pragma unroll
    for (int na = 0; na < 16; na++)
#pragma unroll
        for (int c = 0; c < 4; c++) o[na][c] = 0.f;

    for (int kblk = 0; kblk <= rb; kblk++) {
        const int c0 = kblk * 64;
        __syncthreads();   // previous iteration done reading K/V

        // Load + split K and V (both row-major)
#pragma unroll
        for (int p = 0; p < 16; p++) {
            int id  = tid + p * 128;
            int row = id >> 5;
            int c4  = (id & 31) * 4;
            float4 v = *(const float4*)(kb + (size_t)(c0 + row) * F3E + c4);
            __nv_bfloat16 h0 = __float2bfloat16(v.x), h1 = __float2bfloat16(v.y);
            __nv_bfloat16 h2 = __float2bfloat16(v.z), h3 = __float2bfloat16(v.w);
            __nv_bfloat162* hp = (__nv_bfloat162*)&Kh[row * QKS + c4];
            hp[0] = __halves2bfloat162(h0, h1);
            hp[1] = __halves2bfloat162(h2, h3);
            __nv_bfloat162* lp = (__nv_bfloat162*)&Kl[row * QKS + c4];
            lp[0] = __halves2bfloat162(__float2bfloat16(v.x - __bfloat162float(h0)),
                                       __float2bfloat16(v.y - __bfloat162float(h1)));
            lp[1] = __halves2bfloat162(__float2bfloat16(v.z - __bfloat162float(h2)),
                                       __float2bfloat16(v.w - __bfloat162float(h3)));

            float4 w = *(const float4*)(vb + (size_t)(c0 + row) * F3E + c4);
            __nv_bfloat16 g0 = __float2bfloat16(w.x), g1 = __float2bfloat16(w.y);
            __nv_bfloat16 g2 = __float2bfloat16(w.z), g3 = __float2bfloat16(w.w);
            __nv_bfloat162* vhp = (__nv_bfloat162*)&Vh[row * QKS + c4];
            vhp[0] = __halves2bfloat162(g0, g1);
            vhp[1] = __halves2bfloat162(g2, g3);
            __nv_bfloat162* vlp = (__nv_bfloat162*)&Vl[row * QKS + c4];
            vlp[0] = __halves2bfloat162(__float2bfloat16(w.x - __bfloat162float(g0)),
                                        __float2bfloat16(w.y - __bfloat162float(g1)));
            vlp[1] = __halves2bfloat162(__float2bfloat16(w.z - __bfloat162float(g2)),
                                        __float2bfloat16(w.w - __bfloat162float(g3)));
        }
        __syncthreads();

        // ---- S = Q K^T (3-term, ldmatrix) ----
        float sc[8][4];
#pragma unroll
        for (int nj = 0; nj < 8; nj++)
#pragma unroll
            for (int c = 0; c < 4; c++) sc[nj][c] = 0.f;

#pragma unroll
        for (int ka = 0; ka < 8; ka++) {
            const int kcol = ka * 16;
            uint32_t ah[4], al[4];
            uint32_t aAddr = QhB + (uint32_t)((aRow * QKS + kcol + aKsel) * 2);
            LDSM4(ah, aAddr);
            LDSM4(al, aAddr + (QlB - QhB));
#pragma unroll
            for (int njp = 0; njp < 4; njp++) {
                uint32_t bAddr = KhB +
                    (uint32_t)(((njp * 16 + bRow) * QKS + kcol + bKsel) * 2);
                uint32_t bh4[4], bl4[4];
                LDSM4(bh4, bAddr);
                LDSM4(bl4, bAddr + (KlB - KhB));
                MMA_BF16(sc[2 * njp],     ah, bh4);
                MMA_BF16(sc[2 * njp],     ah, bl4);
                MMA_BF16(sc[2 * njp],     al, bh4);
                MMA_BF16(sc[2 * njp + 1], ah, bh4 + 2);
                MMA_BF16(sc[2 * njp + 1], ah, bl4 + 2);
                MMA_BF16(sc[2 * njp + 1], al, bh4 + 2);
            }
        }

        // ---- scale + causal mask ----
        const bool diag = (kblk == rb);
        const int grow0 = r0 + wid * 16 + gid;
#pragma unroll
        for (int nj = 0; nj < 8; nj++) {
            int col = c0 + nj * 8 + 2 * tig;
            sc[nj][0] *= scale; sc[nj][1] *= scale;
            sc[nj][2] *= scale; sc[nj][3] *= scale;
            if (diag) {
                if (col     > grow0)     sc[nj][0] = -1e30f;
                if (col + 1 > grow0)     sc[nj][1] = -1e30f;
                if (col     > grow0 + 8) sc[nj][2] = -1e30f;
                if (col + 1 > grow0 + 8) sc[nj][3] = -1e30f;
            }
        }

        // ---- online softmax (rows gid, gid+8; quad reduction) ----
        float mx0 = -1e30f, mx1 = -1e30f;
#pragma unroll
        for (int nj = 0; nj < 8; nj++) {
            mx0 = fmaxf(mx0, fmaxf(sc[nj][0], sc[nj][1]));
            mx1 = fmaxf(mx1, fmaxf(sc[nj][2], sc[nj][3]));
        }
        mx0 = fmaxf(mx0, __shfl_xor_sync(0xffffffffu, mx0, 1));
        mx0 = fmaxf(mx0, __shfl_xor_sync(0xffffffffu, mx0, 2));
        mx1 = fmaxf(mx1, __shfl_xor_sync(0xffffffffu, mx1, 1));
        mx1 = fmaxf(mx1, __shfl_xor_sync(0xffffffffu, mx1, 2));

        float mn0 = fmaxf(m0r, mx0);
        float mn1 = fmaxf(m1r, mx1);
        float al0 = __expf(m0r - mn0);
        float al1 = __expf(m1r - mn1);

        float s0 = 0.f, s1 = 0.f;
#pragma unroll
        for (int nj = 0; nj < 8; nj++) {
            sc[nj][0] = __expf(sc[nj][0] - mn0);
            sc[nj][1] = __expf(sc[nj][1] - mn0);
            sc[nj][2] = __expf(sc[nj][2] - mn1);
            sc[nj][3] = __expf(sc[nj][3] - mn1);
            s0 += sc[nj][0] + sc[nj][1];
            s1 += sc[nj][2] + sc[nj][3];
        }
        s0 += __shfl_xor_sync(0xffffffffu, s0, 1);
        s0 += __shfl_xor_sync(0xffffffffu, s0, 2);
        s1 += __shfl_xor_sync(0xffffffffu, s1, 1);
        s1 += __shfl_xor_sync(0xffffffffu, s1, 2);

        l0r = l0r * al0 + s0;
        l1r = l1r * al1 + s1;
        m0r = mn0; m1r = mn1;

#pragma unroll
        for (int na = 0; na < 16; na++) {
            o[na][0] *= al0; o[na][1] *= al0;
            o[na][2] *= al1; o[na][3] *= al1;
        }

        // ---- O += P V (3-term; P from score regs, V via ldmatrix.trans) ----
#pragma unroll
        for (int ka2 = 0; ka2 < 4; ka2++) {
            const int j0 = 2 * ka2, j1 = 2 * ka2 + 1;
            uint32_t aph[4], apl[4];
            {
                float p0 = sc[j0][0], p1 = sc[j0][1];
                float p2 = sc[j0][2], p3 = sc[j0][3];
                float q0 = sc[j1][0], q1 = sc[j1][1];
                float q2 = sc[j1][2], q3 = sc[j1][3];
                aph[0] = pack_bf16(p0, p1);
                aph[1] = pack_bf16(p2, p3);
                aph[2] = pack_bf16(q0, q1);
                aph[3] = pack_bf16(q2, q3);
                __nv_bfloat162 t0 = *(__nv_bfloat162*)&aph[0];
                __nv_bfloat162 t1 = *(__nv_bfloat162*)&aph[1];
                __nv_bfloat162 t2 = *(__nv_bfloat162*)&aph[2];
                __nv_bfloat162 t3 = *(__nv_bfloat162*)&aph[3];
                apl[0] = pack_bf16(p0 - __bfloat162float(t0.x), p1 - __bfloat162float(t0.y));
                apl[1] = pack_bf16(p2 - __bfloat162float(t1.x), p3 - __bfloat162float(t1.y));
                apl[2] = pack_bf16(q0 - __bfloat162float(t2.x), q1 - __bfloat162float(t2.y));
                apl[3] = pack_bf16(q2 - __bfloat162float(t3.x), q3 - __bfloat162float(t3.y));
            }
            const int t0row = ka2 * 16;
#pragma unroll
            for (int nap = 0; nap < 8; nap++) {
                uint32_t vAddr = VhB +
                    (uint32_t)(((t0row + vTrow) * QKS + nap * 16 + vDsel) * 2);
                uint32_t bh4[4], bl4[4];
                LDSM4T(bh4, vAddr);
                LDSM4T(bl4, vAddr + (VlB - VhB));
                MMA_BF16(o[2 * nap],     aph, bh4);
                MMA_BF16(o[2 * nap],     aph, bl4);
                MMA_BF16(o[2 * nap],     apl, bh4);
                MMA_BF16(o[2 * nap + 1], aph, bh4 + 2);
                MMA_BF16(o[2 * nap + 1], aph, bl4 + 2);
                MMA_BF16(o[2 * nap + 1], apl, bh4 + 2);
            }
        }
    }

    // ---- epilogue: normalize, write ctx ----
    float inv0 = 1.f / l0r;
    float inv1 = 1.f / l1r;
    int row = r0 + wid * 16 + gid;
    float* op0 = ctx + ((size_t)b * SEQ + row) * EMB + (size_t)h * HDIM;
    float* op1 = ctx + ((size_t)b * SEQ + row + 8) * EMB + (size_t)h * HDIM;
#pragma unroll
    for (int na = 0; na < 16; na++) {
        int col = na * 8 + 2 * tig;
        *(float2*)(op0 + col) = make_float2(o[na][0] * inv0, o[na][1] * inv0);
        *(float2*)(op1 + col) = make_float2(o[na][2] * inv1, o[na][3] * inv1);
    }
}

// ---------------------------------------------------------------------------
// Launch
// ---------------------------------------------------------------------------
extern "C" void kernel_launch(void* const* d_in, const int* in_sizes, int n_in,
                              void* d_out, int out_size)
{
    const float* x      = (const float*)d_in[0];
    const float* wqkv_w = (const float*)d_in[1];
    const float* wqkv_b = (const float*)d_in[2];
    const float* out_w  = (const float*)d_in[3];
    const float* out_b  = (const float*)d_in[4];
    float* out = (float*)d_out;

    float *qkv, *ctx;
    __nv_bfloat16 *xh, *xl, *wqh, *wql, *owh, *owl, *ch, *cl;
    cudaGetSymbolAddress((void**)&qkv, g_qkv);
    cudaGetSymbolAddress((void**)&ctx, g_ctx);
    cudaGetSymbolAddress((void**)&xh, g_xh);
    cudaGetSymbolAddress((void**)&xl, g_xl);
    cudaGetSymbolAddress((void**)&wqh, g_wqh);
    cudaGetSymbolAddress((void**)&wql, g_wql);
    cudaGetSymbolAddress((void**)&owh, g_owh);
    cudaGetSymbolAddress((void**)&owl, g_owl);
    cudaGetSymbolAddress((void**)&ch, g_ch);
    cudaGetSymbolAddress((void**)&cl, g_cl);

    cudaFuncSetAttribute(gemm_mma_bf16x3,
                         cudaFuncAttributeMaxDynamicSharedMemorySize, GEMM_SMEM);
    cudaFuncSetAttribute(flash_mma_kernel,
                         cudaFuncAttributeMaxDynamicSharedMemorySize, FLASH_SMEM);

    // 0) Split inputs to bf16 hi/lo
    {
        int n4 = (MTOT * EMB) / 4;
        split_kernel<<<(n4 + 255) / 256, 256>>>(x, xh, xl, n4);
    }
    {
        int n4 = (F3E * EMB) / 4;
        split_kernel<<<(n4 + 255) / 256, 256>>>(wqkv_w, wqh, wql, n4);
    }
    {
        int n4 = (EMB * EMB) / 4;
        split_kernel<<<(n4 + 255) / 256, 256>>>(out_w, owh, owl, n4);
    }

    // 1) QKV projection: [4096,2048] x [6144,2048]^T
    gemm_mma_bf16x3<<<dim3(F3E / 128, MTOT / 128), 256, GEMM_SMEM>>>(
        xh, xl, wqh, wql, wqkv_b, qkv, MTOT, F3E, EMB);

    // 2) RoPE
    rope_kernel<<<(BATCH * SEQ * NHEAD * 64) / 256, 256>>>(qkv);

    // 3) Causal flash attention (mma.sync bf16x3 + ldmatrix)
    flash_mma_kernel<<<dim3(SEQ / 64, NHEAD, BATCH), 128, FLASH_SMEM>>>(qkv, ctx);

    // 4) Split ctx, output projection
    {
        int n4 = (MTOT * EMB) / 4;
        split_kernel<<<(n4 + 255) / 256, 256>>>(ctx, ch, cl, n4);
    }
    gemm_mma_bf16x3<<<dim3(EMB / 128, MTOT / 128), 256, GEMM_SMEM>>>(
        ch, cl, owh, owl, out_b, out, MTOT, EMB, EMB);
}